// round 7
// baseline (speedup 1.0000x reference)
#include <cuda_runtime.h>
#include <cuda_bf16.h>
#include <cstdint>

#define B_T    16000
#define D_IN   320
#define E_DIM  16
#define K_CB   8192
#define KS2    4
#define CANDS  (K_CB / KS2)        // 2048 cands per kseg
#define NT     64                  // cands per smem tile
#define TILES  (CANDS / NT)        // 32
#define GRID_R (B_T / 128)         // 125

// ---- scratch (device globals: the sanctioned no-alloc path) ----
__device__ __align__(16) unsigned short g_A[B_T * 128];    // bf16 split-A (K=128), 4 MB
__device__ __align__(16) unsigned short g_Bs[K_CB * 128];  // bf16 split-B, 2 MB
__device__ float g_pv[KS2 * B_T];
__device__ int   g_pi[KS2 * B_T];

// ---------------------------------------------------------------------------
__device__ __forceinline__ uint32_t smem_u32(const void* p) {
    uint32_t a;
    asm("{ .reg .u64 t; cvta.to.shared.u64 t, %1; cvt.u32.u64 %0, t; }" : "=r"(a) : "l"(p));
    return a;
}
__device__ __forceinline__ void cpasync16(uint32_t dst, const void* src) {
    asm volatile("cp.async.cg.shared.global [%0], [%1], 16;" :: "r"(dst), "l"(src));
}
__device__ __forceinline__ void cp_commit() {
    asm volatile("cp.async.commit_group;" ::: "memory");
}
__device__ __forceinline__ void cp_wait0() {
    asm volatile("cp.async.wait_group 0;" ::: "memory");
}
__device__ __forceinline__ uint32_t lds32(uint32_t a) {
    uint32_t v; asm volatile("ld.shared.b32 %0, [%1];" : "=r"(v) : "r"(a)); return v;
}
// m16n8k16 row.col bf16 -> f32 accumulate (sm_80+, valid on base sm_100)
__device__ __forceinline__ void mma16816(float* d, const uint32_t* a, uint32_t b0, uint32_t b1) {
    asm volatile(
        "mma.sync.aligned.m16n8k16.row.col.f32.bf16.bf16.f32 "
        "{%0,%1,%2,%3}, {%4,%5,%6,%7}, {%8,%9}, {%0,%1,%2,%3};"
        : "+f"(d[0]), "+f"(d[1]), "+f"(d[2]), "+f"(d[3])
        : "r"(a[0]), "r"(a[1]), "r"(a[2]), "r"(a[3]), "r"(b0), "r"(b1));
}

// ============================================================================
// Kernel 1: projection (fp32) fused with bf16 3-split.
// Block: 256 thr, 64 rows. H staged coalesced to smem (stride 328 floats for
// bank spread); thread = (2 rows) x (2 e's); fp32 fmaf; then split -> g_A.
// A group layout per row (8 groups x 16 bf16): [v1,v1,v1,v2,v2,v3,v2,v3].
// ============================================================================
#define HS_STR 328
#define PROJ_SMEM ((5120 + 64 * HS_STR) * 4)
__global__ __launch_bounds__(256) void proj_split_kernel(const float* __restrict__ H,
                                                         const float* __restrict__ P) {
    extern __shared__ float psm[];
    float* Ps = psm;                 // 5120 floats
    float* Hs = psm + 5120;          // 64 * 328 floats
    const int tid = threadIdx.x;
    const int rb  = blockIdx.x * 64;

    {   // stage P (coalesced)
        const float4* Pg = (const float4*)P;
        float4* Ps4 = (float4*)Ps;
        for (int i = tid; i < 1280; i += 256) Ps4[i] = Pg[i];
    }
    {   // stage H: 64 rows x 80 float4, coalesced reads, padded rows
        const float4* Hg = (const float4*)H + (size_t)rb * 80;
        for (int i = tid; i < 5120; i += 256) {
            int r = i / 80, f = i % 80;
            *(float4*)&Hs[r * HS_STR + f * 4] = Hg[(size_t)r * 80 + f];
        }
    }
    __syncthreads();

    const int rloc = tid >> 3;      // 0..31
    const int l    = tid & 7;       // e-pair index
    float acc[2][2] = {{0.f, 0.f}, {0.f, 0.f}};
    const float* h0 = &Hs[rloc * HS_STR];
    const float* h1 = &Hs[(rloc + 32) * HS_STR];
    const float* pb = &Ps[2 * l];

#pragma unroll 4
    for (int d4 = 0; d4 < 80; ++d4) {
        float ha[4], hb[4];
        *(float4*)ha = *(const float4*)&h0[d4 * 4];
        *(float4*)hb = *(const float4*)&h1[d4 * 4];
#pragma unroll
        for (int j = 0; j < 4; ++j) {
            float2 p = *(const float2*)&pb[(d4 * 4 + j) * 16];
            acc[0][0] = fmaf(ha[j], p.x, acc[0][0]);
            acc[0][1] = fmaf(ha[j], p.y, acc[0][1]);
            acc[1][0] = fmaf(hb[j], p.x, acc[1][0]);
            acc[1][1] = fmaf(hb[j], p.y, acc[1][1]);
        }
    }

    const int ag[8] = {0, 0, 0, 1, 1, 2, 1, 2};
#pragma unroll
    for (int r = 0; r < 2; ++r) {
        unsigned short s[3][2];
#pragma unroll
        for (int e = 0; e < 2; ++e) {
            float v = acc[r][e];
            __nv_bfloat16 b1 = __float2bfloat16(v);
            float r1 = v - __bfloat162float(b1);
            __nv_bfloat16 b2 = __float2bfloat16(r1);
            float r2 = r1 - __bfloat162float(b2);
            __nv_bfloat16 b3 = __float2bfloat16(r2);
            s[0][e] = __bfloat16_as_ushort(b1);
            s[1][e] = __bfloat16_as_ushort(b2);
            s[2][e] = __bfloat16_as_ushort(b3);
        }
        unsigned short* dst = g_A + (size_t)(rb + rloc + r * 32) * 128 + 2 * l;
#pragma unroll
        for (int g = 0; g < 8; ++g)
            *(ushort2*)(dst + g * 16) = make_ushort2(s[ag[g]][0], s[ag[g]][1]);
    }
}

// ============================================================================
// Kernel 2: codebook bf16 3-split.  B groups: [c1,c2,c3,c1,c2,c1,c3,c2].
// ============================================================================
__global__ __launch_bounds__(256) void cb_split_kernel(const float* __restrict__ CB) {
    int r = blockIdx.x * 256 + threadIdx.x;
    if (r >= K_CB) return;
    unsigned short s[3][E_DIM];
#pragma unroll
    for (int e = 0; e < E_DIM; ++e) {
        float v = CB[(size_t)r * E_DIM + e];
        __nv_bfloat16 b1 = __float2bfloat16(v);
        float r1 = v - __bfloat162float(b1);
        __nv_bfloat16 b2 = __float2bfloat16(r1);
        float r2 = r1 - __bfloat162float(b2);
        __nv_bfloat16 b3 = __float2bfloat16(r2);
        s[0][e] = __bfloat16_as_ushort(b1);
        s[1][e] = __bfloat16_as_ushort(b2);
        s[2][e] = __bfloat16_as_ushort(b3);
    }
    const int bg[8] = {0, 1, 2, 0, 1, 0, 2, 1};
    ushort4* dst = (ushort4*)(g_Bs + (size_t)r * 128);
#pragma unroll
    for (int g = 0; g < 8; ++g)
#pragma unroll
        for (int q = 0; q < 4; ++q)
            dst[g * 4 + q] = make_ushort4(s[bg[g]][4 * q], s[bg[g]][4 * q + 1],
                                          s[bg[g]][4 * q + 2], s[bg[g]][4 * q + 3]);
}

// ============================================================================
// Kernel 3: mma.sync bf16 score + fused in-register argmax.
// 128 thr (4 warps x 32 rows), grid (125, 4 ksegs).  K=128 (8 k-steps).
// Smem rows 256B; 16B units stored at unit^(row&7) -> conflict-free frag LDS.
// A: staged once, held in 64 regs.  B: double-buffered 64-cand cp.async tiles.
// ============================================================================
#define SM_A  0
#define SM_B0 32768
#define SM_B1 49152
#define SCORE_SMEM 65536

__device__ __forceinline__ void stage_B(uint32_t sb_buf, int cand0, int tid) {
    const char* src = (const char*)g_Bs + (size_t)(cand0 + (tid >> 1)) * 256 + (tid & 1) * 128;
    uint32_t dstrow = sb_buf + (tid >> 1) * 256;
    int r7 = (tid >> 1) & 7;
#pragma unroll
    for (int j = 0; j < 8; ++j) {
        int u = (tid & 1) * 8 + j;
        cpasync16(dstrow + ((u ^ r7) << 4), src + j * 16);
    }
}

__global__ __launch_bounds__(128) void mma_score_kernel() {
    extern __shared__ char smem[];
    const uint32_t sb = smem_u32(smem);
    const int tid  = threadIdx.x;
    const int lane = tid & 31;
    const int warp = tid >> 5;
    const int rb   = blockIdx.x * 128;
    const int kseg = blockIdx.y;
    const int kb0  = kseg * CANDS;

    // stage A (128 rows x 256B), swizzled
    {
        const char* src = (const char*)g_A + (size_t)(rb + tid) * 256;
        uint32_t dst = sb + SM_A + tid * 256;
        int r7 = tid & 7;
#pragma unroll
        for (int u = 0; u < 16; ++u) cpasync16(dst + ((u ^ r7) << 4), src + u * 16);
    }
    stage_B(sb + SM_B0, kb0, tid);
    cp_commit();
    cp_wait0();
    __syncthreads();

    // load A fragments: a[mg][kk][4]
    uint32_t a[2][8][4];
    const int q  = lane >> 2;       // 0..7
    const int c4 = lane & 3;
#pragma unroll
    for (int mg = 0; mg < 2; ++mg) {
        int R0 = warp * 32 + mg * 16 + q;
        int R1 = R0 + 8;
        uint32_t base0 = sb + SM_A + R0 * 256 + c4 * 4;
        uint32_t base1 = sb + SM_A + R1 * 256 + c4 * 4;
        int x0 = R0 & 7, x1 = R1 & 7;
#pragma unroll
        for (int kk = 0; kk < 8; ++kk) {
            a[mg][kk][0] = lds32(base0 + (((2 * kk)     ^ x0) << 4));
            a[mg][kk][1] = lds32(base1 + (((2 * kk)     ^ x1) << 4));
            a[mg][kk][2] = lds32(base0 + (((2 * kk + 1) ^ x0) << 4));
            a[mg][kk][3] = lds32(base1 + (((2 * kk + 1) ^ x1) << 4));
        }
    }
    __syncthreads();

    float best[4]; int bid[4];
#pragma unroll
    for (int s = 0; s < 4; ++s) { best[s] = __int_as_float(0xff800000); bid[s] = 0; }

    for (int t = 0; t < TILES; ++t) {
        uint32_t buf = sb + ((t & 1) ? SM_B1 : SM_B0);
        if (t + 1 < TILES) {
            stage_B(sb + (((t + 1) & 1) ? SM_B1 : SM_B0), kb0 + (t + 1) * NT, tid);
            cp_commit();
        }
#pragma unroll 2
        for (int g = 0; g < NT / 8; ++g) {
            float d0[4] = {0.f, 0.f, 0.f, 0.f};
            float d1[4] = {0.f, 0.f, 0.f, 0.f};
            uint32_t cbase = buf + (g * 8 + q) * 256 + c4 * 4;
#pragma unroll
            for (int kk = 0; kk < 8; ++kk) {
                uint32_t b0 = lds32(cbase + (((2 * kk)     ^ q) << 4));
                uint32_t b1 = lds32(cbase + (((2 * kk + 1) ^ q) << 4));
                mma16816(d0, a[0][kk], b0, b1);
                mma16816(d1, a[1][kk], b0, b1);
            }
            const int kb = kb0 + t * NT + g * 8 + 2 * c4;
            // mg0: slots 0 (row R0), 1 (R0+8); mg1: slots 2,3.  Ascending k, strict >.
            if (d0[0] > best[0]) { best[0] = d0[0]; bid[0] = kb; }
            if (d0[1] > best[0]) { best[0] = d0[1]; bid[0] = kb + 1; }
            if (d0[2] > best[1]) { best[1] = d0[2]; bid[1] = kb; }
            if (d0[3] > best[1]) { best[1] = d0[3]; bid[1] = kb + 1; }
            if (d1[0] > best[2]) { best[2] = d1[0]; bid[2] = kb; }
            if (d1[1] > best[2]) { best[2] = d1[1]; bid[2] = kb + 1; }
            if (d1[2] > best[3]) { best[3] = d1[2]; bid[3] = kb; }
            if (d1[3] > best[3]) { best[3] = d1[3]; bid[3] = kb + 1; }
        }
        if (t + 1 < TILES) cp_wait0();
        __syncthreads();
    }

    // reduce across the 4 lanes of each quad (same rows, disjoint n-residues)
#pragma unroll
    for (int s = 0; s < 4; ++s) {
#pragma unroll
        for (int off = 1; off <= 2; off <<= 1) {
            float ov = __shfl_xor_sync(0xFFFFFFFFu, best[s], off);
            int   oi = __shfl_xor_sync(0xFFFFFFFFu, bid[s],  off);
            if (ov > best[s] || (ov == best[s] && oi < bid[s])) { best[s] = ov; bid[s] = oi; }
        }
    }
    if (c4 == 0) {
#pragma unroll
        for (int s = 0; s < 4; ++s) {
            int row = warp * 32 + (s >> 1) * 16 + (s & 1) * 8 + q;
            g_pv[(size_t)kseg * B_T + rb + row] = best[s];
            g_pi[(size_t)kseg * B_T + rb + row] = bid[s];
        }
    }
}

// ============================================================================
// Kernel 4: combine KS2 partials; label written as float VALUE (output buffer
// is float32 — int bit patterns read as denormals: the round-1/2 bug).
// ============================================================================
__global__ __launch_bounds__(256) void combine_kernel(float* __restrict__ out) {
    int row = blockIdx.x * 256 + threadIdx.x;
    if (row >= B_T) return;
    float bv = g_pv[row];
    int   bi = g_pi[row];
#pragma unroll
    for (int s = 1; s < KS2; ++s) {
        float v = g_pv[(size_t)s * B_T + row];
        int   i = g_pi[(size_t)s * B_T + row];
        if (v > bv || (v == bv && i < bi)) { bv = v; bi = i; }
    }
    out[row] = (float)bi;
}

// ============================================================================
extern "C" void kernel_launch(void* const* d_in, const int* in_sizes, int n_in,
                              void* d_out, int out_size) {
    // Input dispatch by element count (ordering-proof):
    //   H = 5,120,000 ; P = 5,120 ; CB = 131,072
    const float* H  = nullptr;
    const float* P  = nullptr;
    const float* CB = nullptr;
    for (int i = 0; i < n_in; ++i) {
        if      (in_sizes[i] == B_T * D_IN)   H  = (const float*)d_in[i];
        else if (in_sizes[i] == D_IN * E_DIM) P  = (const float*)d_in[i];
        else if (in_sizes[i] == K_CB * E_DIM) CB = (const float*)d_in[i];
    }
    if (!H)  H  = (const float*)d_in[0];
    if (!P)  P  = (const float*)d_in[1];
    if (!CB) CB = (const float*)d_in[2];

    float* out = (float*)d_out;

    static int init = 0;
    if (!init) {
        cudaFuncSetAttribute(proj_split_kernel, cudaFuncAttributeMaxDynamicSharedMemorySize, PROJ_SMEM);
        cudaFuncSetAttribute(mma_score_kernel,  cudaFuncAttributeMaxDynamicSharedMemorySize, SCORE_SMEM);
        init = 1;
    }

    proj_split_kernel<<<B_T / 64, 256, PROJ_SMEM>>>(H, P);
    cb_split_kernel<<<K_CB / 256, 256>>>(CB);
    mma_score_kernel<<<dim3(GRID_R, KS2), 128, SCORE_SMEM>>>();
    combine_kernel<<<(B_T + 255) / 256, 256>>>(out);
}

// round 8
// speedup vs baseline: 1.1260x; 1.1260x over previous
#include <cuda_runtime.h>
#include <cuda_bf16.h>
#include <cstdint>

#define B_T    16000
#define D_IN   320
#define E_DIM  16
#define K_CB   8192
#define KS2    8
#define CANDS  (K_CB / KS2)        // 1024 cands per kseg
#define NT     64                  // cands per smem tile
#define TILES  (CANDS / NT)        // 16
#define GRID_R (B_T / 128)         // 125

// ---- scratch (device globals: the sanctioned no-alloc path) ----
__device__ __align__(16) unsigned short g_A[B_T * 128];    // bf16 split-A (K=128), 4 MB
__device__ __align__(16) unsigned short g_Bs[K_CB * 128];  // bf16 split-B, 2 MB
__device__ float g_pv[KS2 * B_T];
__device__ int   g_pi[KS2 * B_T];

// ---------------------------------------------------------------------------
__device__ __forceinline__ uint32_t smem_u32(const void* p) {
    uint32_t a;
    asm("{ .reg .u64 t; cvta.to.shared.u64 t, %1; cvt.u32.u64 %0, t; }" : "=r"(a) : "l"(p));
    return a;
}
__device__ __forceinline__ void cpasync16(uint32_t dst, const void* src) {
    asm volatile("cp.async.cg.shared.global [%0], [%1], 16;" :: "r"(dst), "l"(src));
}
__device__ __forceinline__ void cp_commit() {
    asm volatile("cp.async.commit_group;" ::: "memory");
}
__device__ __forceinline__ void cp_wait0() {
    asm volatile("cp.async.wait_group 0;" ::: "memory");
}
__device__ __forceinline__ uint32_t lds32(uint32_t a) {
    uint32_t v; asm volatile("ld.shared.b32 %0, [%1];" : "=r"(v) : "r"(a)); return v;
}
// m16n8k16 row.col bf16 -> f32 accumulate (sm_80+, valid on base sm_100)
__device__ __forceinline__ void mma16816(float* d, const uint32_t* a, uint32_t b0, uint32_t b1) {
    asm volatile(
        "mma.sync.aligned.m16n8k16.row.col.f32.bf16.bf16.f32 "
        "{%0,%1,%2,%3}, {%4,%5,%6,%7}, {%8,%9}, {%0,%1,%2,%3};"
        : "+f"(d[0]), "+f"(d[1]), "+f"(d[2]), "+f"(d[3])
        : "r"(a[0]), "r"(a[1]), "r"(a[2]), "r"(a[3]), "r"(b0), "r"(b1));
}

// ============================================================================
// Kernel 1: projection (fp32), warp-per-row, fused bf16 3-split.
// Lane l covers d = l, l+32, ..., l+288 (coalesced LDG.32); P in smem with
// stride-17 padding (conflict-free scalar LDS); 5-level butterfly gives every
// lane the full row; lanes 0-15 split + write.
// A group layout per row (8 groups x 16 bf16): [v1,v1,v1,v2,v2,v3,v2,v3].
// ============================================================================
#define PS_STR 17
__global__ __launch_bounds__(256) void proj_split_kernel(const float* __restrict__ H,
                                                         const float* __restrict__ P) {
    __shared__ float Ps[D_IN * PS_STR];      // 21760 B
    const int tid = threadIdx.x;
    for (int i = tid; i < D_IN * E_DIM; i += 256) {
        int d = i >> 4, e = i & 15;
        Ps[d * PS_STR + e] = P[i];
    }
    __syncthreads();

    const int warp = tid >> 5;
    const int lane = tid & 31;
    const int row  = blockIdx.x * 8 + warp;

    float acc[E_DIM];
#pragma unroll
    for (int e = 0; e < E_DIM; ++e) acc[e] = 0.0f;

    const float* h = H + (size_t)row * D_IN;
#pragma unroll
    for (int i = 0; i < 10; ++i) {
        float hv = h[i * 32 + lane];
        const float* p = &Ps[(i * 32 + lane) * PS_STR];
#pragma unroll
        for (int e = 0; e < E_DIM; ++e) acc[e] = fmaf(hv, p[e], acc[e]);
    }
#pragma unroll
    for (int off = 16; off >= 1; off >>= 1)
#pragma unroll
        for (int e = 0; e < E_DIM; ++e)
            acc[e] += __shfl_xor_sync(0xFFFFFFFFu, acc[e], off);

    if (lane < E_DIM) {
        float v = acc[lane];
        __nv_bfloat16 b1 = __float2bfloat16(v);
        float r1 = v - __bfloat162float(b1);
        __nv_bfloat16 b2 = __float2bfloat16(r1);
        float r2 = r1 - __bfloat162float(b2);
        __nv_bfloat16 b3 = __float2bfloat16(r2);
        unsigned short s[3] = { __bfloat16_as_ushort(b1), __bfloat16_as_ushort(b2),
                                __bfloat16_as_ushort(b3) };
        const int ag[8] = {0, 0, 0, 1, 1, 2, 1, 2};
        unsigned short* dst = g_A + (size_t)row * 128 + lane;
#pragma unroll
        for (int g = 0; g < 8; ++g) dst[g * 16] = s[ag[g]];
    }
}

// ============================================================================
// Kernel 2: codebook bf16 3-split.  B groups: [c1,c2,c3,c1,c2,c1,c3,c2].
// ============================================================================
__global__ __launch_bounds__(256) void cb_split_kernel(const float* __restrict__ CB) {
    int r = blockIdx.x * 256 + threadIdx.x;
    if (r >= K_CB) return;
    unsigned short s[3][E_DIM];
#pragma unroll
    for (int e = 0; e < E_DIM; ++e) {
        float v = CB[(size_t)r * E_DIM + e];
        __nv_bfloat16 b1 = __float2bfloat16(v);
        float r1 = v - __bfloat162float(b1);
        __nv_bfloat16 b2 = __float2bfloat16(r1);
        float r2 = r1 - __bfloat162float(b2);
        __nv_bfloat16 b3 = __float2bfloat16(r2);
        s[0][e] = __bfloat16_as_ushort(b1);
        s[1][e] = __bfloat16_as_ushort(b2);
        s[2][e] = __bfloat16_as_ushort(b3);
    }
    const int bg[8] = {0, 1, 2, 0, 1, 0, 2, 1};
    ushort4* dst = (ushort4*)(g_Bs + (size_t)r * 128);
#pragma unroll
    for (int g = 0; g < 8; ++g)
#pragma unroll
        for (int q = 0; q < 4; ++q)
            dst[g * 4 + q] = make_ushort4(s[bg[g]][4 * q], s[bg[g]][4 * q + 1],
                                          s[bg[g]][4 * q + 2], s[bg[g]][4 * q + 3]);
}

// ============================================================================
// Kernel 3: mma.sync bf16 score + fused in-register argmax.
// 128 thr (4 warps x 32 rows), grid (125, 8).  K=128 (8 k-steps).
// Validated round-7 fragment/swizzle mapping, restructured for ILP/occupancy:
//  - 4 independent HMMA chains per warp (two n-groups in flight)
//  - A-stage smem reused as B1 buffer after fragments are in registers
//    (48 KB static smem -> 4 blocks/SM; launch_bounds(128,4))
// ============================================================================
#define SM_A  0
#define SM_B0 32768
#define SM_B1 0           // reuses A space once fragments are loaded

__device__ __forceinline__ void stage_B(uint32_t sb_buf, int cand0, int tid) {
    const char* src = (const char*)g_Bs + (size_t)(cand0 + (tid >> 1)) * 256 + (tid & 1) * 128;
    uint32_t dstrow = sb_buf + (tid >> 1) * 256;
    int r7 = (tid >> 1) & 7;
#pragma unroll
    for (int j = 0; j < 8; ++j) {
        int u = (tid & 1) * 8 + j;
        cpasync16(dstrow + ((u ^ r7) << 4), src + j * 16);
    }
}

__global__ __launch_bounds__(128, 4) void mma_score_kernel() {
    __shared__ __align__(16) char smem[49152];
    const uint32_t sb = smem_u32(smem);
    const int tid  = threadIdx.x;
    const int lane = tid & 31;
    const int warp = tid >> 5;
    const int rb   = blockIdx.x * 128;
    const int kseg = blockIdx.y;
    const int kb0  = kseg * CANDS;

    // stage A (128 rows x 256B), swizzled
    {
        const char* src = (const char*)g_A + (size_t)(rb + tid) * 256;
        uint32_t dst = sb + SM_A + tid * 256;
        int r7 = tid & 7;
#pragma unroll
        for (int u = 0; u < 16; ++u) cpasync16(dst + ((u ^ r7) << 4), src + u * 16);
    }
    stage_B(sb + SM_B0, kb0, tid);
    cp_commit();
    cp_wait0();
    __syncthreads();

    // load A fragments: a[mg][kk][4]
    uint32_t a[2][8][4];
    const int q  = lane >> 2;       // 0..7
    const int c4 = lane & 3;
#pragma unroll
    for (int mg = 0; mg < 2; ++mg) {
        int R0 = warp * 32 + mg * 16 + q;
        int R1 = R0 + 8;
        uint32_t base0 = sb + SM_A + R0 * 256 + c4 * 4;
        uint32_t base1 = sb + SM_A + R1 * 256 + c4 * 4;
        int x0 = R0 & 7, x1 = R1 & 7;
#pragma unroll
        for (int kk = 0; kk < 8; ++kk) {
            a[mg][kk][0] = lds32(base0 + (((2 * kk)     ^ x0) << 4));
            a[mg][kk][1] = lds32(base1 + (((2 * kk)     ^ x1) << 4));
            a[mg][kk][2] = lds32(base0 + (((2 * kk + 1) ^ x0) << 4));
            a[mg][kk][3] = lds32(base1 + (((2 * kk + 1) ^ x1) << 4));
        }
    }
    __syncthreads();    // all warps done reading A smem -> B1 may overwrite it

    float best[4]; int bid[4];
#pragma unroll
    for (int s = 0; s < 4; ++s) { best[s] = __int_as_float(0xff800000); bid[s] = 0; }

    for (int t = 0; t < TILES; ++t) {
        uint32_t buf = sb + ((t & 1) ? SM_B1 : SM_B0);
        if (t + 1 < TILES) {
            stage_B(sb + (((t + 1) & 1) ? SM_B1 : SM_B0), kb0 + (t + 1) * NT, tid);
            cp_commit();
        }
        // 8 n-groups per tile, processed in pairs -> 4 independent HMMA chains
#pragma unroll
        for (int gg = 0; gg < 4; ++gg) {
            const int g0 = 2 * gg, g1 = 2 * gg + 1;
            float d[4][4] = {{0.f,0.f,0.f,0.f},{0.f,0.f,0.f,0.f},
                             {0.f,0.f,0.f,0.f},{0.f,0.f,0.f,0.f}};
            uint32_t cb0 = buf + (g0 * 8 + q) * 256 + c4 * 4;
            uint32_t cb1 = buf + (g1 * 8 + q) * 256 + c4 * 4;
#pragma unroll
            for (int kk = 0; kk < 8; ++kk) {
                uint32_t b00 = lds32(cb0 + (((2 * kk)     ^ q) << 4));
                uint32_t b01 = lds32(cb0 + (((2 * kk + 1) ^ q) << 4));
                uint32_t b10 = lds32(cb1 + (((2 * kk)     ^ q) << 4));
                uint32_t b11 = lds32(cb1 + (((2 * kk + 1) ^ q) << 4));
                mma16816(d[0], a[0][kk], b00, b01);
                mma16816(d[1], a[1][kk], b00, b01);
                mma16816(d[2], a[0][kk], b10, b11);
                mma16816(d[3], a[1][kk], b10, b11);
            }
            // compares in ascending-k order: group g0 then g1 (strict > = first-max)
            const int kA = kb0 + t * NT + g0 * 8 + 2 * c4;
            if (d[0][0] > best[0]) { best[0] = d[0][0]; bid[0] = kA; }
            if (d[0][1] > best[0]) { best[0] = d[0][1]; bid[0] = kA + 1; }
            if (d[0][2] > best[1]) { best[1] = d[0][2]; bid[1] = kA; }
            if (d[0][3] > best[1]) { best[1] = d[0][3]; bid[1] = kA + 1; }
            if (d[1][0] > best[2]) { best[2] = d[1][0]; bid[2] = kA; }
            if (d[1][1] > best[2]) { best[2] = d[1][1]; bid[2] = kA + 1; }
            if (d[1][2] > best[3]) { best[3] = d[1][2]; bid[3] = kA; }
            if (d[1][3] > best[3]) { best[3] = d[1][3]; bid[3] = kA + 1; }
            const int kB = kA + 8;
            if (d[2][0] > best[0]) { best[0] = d[2][0]; bid[0] = kB; }
            if (d[2][1] > best[0]) { best[0] = d[2][1]; bid[0] = kB + 1; }
            if (d[2][2] > best[1]) { best[1] = d[2][2]; bid[1] = kB; }
            if (d[2][3] > best[1]) { best[1] = d[2][3]; bid[1] = kB + 1; }
            if (d[3][0] > best[2]) { best[2] = d[3][0]; bid[2] = kB; }
            if (d[3][1] > best[2]) { best[2] = d[3][1]; bid[2] = kB + 1; }
            if (d[3][2] > best[3]) { best[3] = d[3][2]; bid[3] = kB; }
            if (d[3][3] > best[3]) { best[3] = d[3][3]; bid[3] = kB + 1; }
        }
        if (t + 1 < TILES) cp_wait0();
        __syncthreads();
    }

    // reduce across the 4 lanes of each quad (same rows, disjoint n-residues)
#pragma unroll
    for (int s = 0; s < 4; ++s) {
#pragma unroll
        for (int off = 1; off <= 2; off <<= 1) {
            float ov = __shfl_xor_sync(0xFFFFFFFFu, best[s], off);
            int   oi = __shfl_xor_sync(0xFFFFFFFFu, bid[s],  off);
            if (ov > best[s] || (ov == best[s] && oi < bid[s])) { best[s] = ov; bid[s] = oi; }
        }
    }
    if (c4 == 0) {
#pragma unroll
        for (int s = 0; s < 4; ++s) {
            int row = warp * 32 + (s >> 1) * 16 + (s & 1) * 8 + q;
            g_pv[(size_t)kseg * B_T + rb + row] = best[s];
            g_pi[(size_t)kseg * B_T + rb + row] = bid[s];
        }
    }
}

// ============================================================================
// Kernel 4: combine KS2 partials; label written as float VALUE (output buffer
// is float32 — int bit patterns read as denormals: the round-1/2 bug).
// ============================================================================
__global__ __launch_bounds__(256) void combine_kernel(float* __restrict__ out) {
    int row = blockIdx.x * 256 + threadIdx.x;
    if (row >= B_T) return;
    float bv = g_pv[row];
    int   bi = g_pi[row];
#pragma unroll
    for (int s = 1; s < KS2; ++s) {
        float v = g_pv[(size_t)s * B_T + row];
        int   i = g_pi[(size_t)s * B_T + row];
        if (v > bv || (v == bv && i < bi)) { bv = v; bi = i; }
    }
    out[row] = (float)bi;
}

// ============================================================================
extern "C" void kernel_launch(void* const* d_in, const int* in_sizes, int n_in,
                              void* d_out, int out_size) {
    // Input dispatch by element count (ordering-proof):
    //   H = 5,120,000 ; P = 5,120 ; CB = 131,072
    const float* H  = nullptr;
    const float* P  = nullptr;
    const float* CB = nullptr;
    for (int i = 0; i < n_in; ++i) {
        if      (in_sizes[i] == B_T * D_IN)   H  = (const float*)d_in[i];
        else if (in_sizes[i] == D_IN * E_DIM) P  = (const float*)d_in[i];
        else if (in_sizes[i] == K_CB * E_DIM) CB = (const float*)d_in[i];
    }
    if (!H)  H  = (const float*)d_in[0];
    if (!P)  P  = (const float*)d_in[1];
    if (!CB) CB = (const float*)d_in[2];

    float* out = (float*)d_out;

    proj_split_kernel<<<B_T / 8, 256>>>(H, P);
    cb_split_kernel<<<K_CB / 256, 256>>>(CB);
    mma_score_kernel<<<dim3(GRID_R, KS2), 128>>>();
    combine_kernel<<<(B_T + 255) / 256, 256>>>(out);
}

// round 9
// speedup vs baseline: 1.1527x; 1.0237x over previous
#include <cuda_runtime.h>
#include <cuda_bf16.h>
#include <cstdint>

#define B_T    16000
#define D_IN   320
#define E_DIM  16
#define K_CB   8192
#define KS2    8
#define CANDS  (K_CB / KS2)        // 1024 cands per kseg
#define NT     64                  // cands per tile (32 MMA + 32 FFMA)
#define TILES  (CANDS / NT)        // 16
#define ROWS_PB 64
#define GRID_R (B_T / ROWS_PB)     // 250
#define NSLOT  (2 * KS2)           // 8 MMA slots + 8 FFMA slots

// ---- scratch (device globals: the sanctioned no-alloc path) ----
__device__ __align__(16) unsigned short g_A[B_T * 128];    // bf16 split-A (K=128), 4 MB
__device__ __align__(16) unsigned short g_Bs[K_CB * 128];  // bf16 split-B, 2 MB
__device__ __align__(16) float g_V[B_T * E_DIM];           // fp32 projected rows, 1 MB
__device__ float g_pv[NSLOT * B_T];
__device__ int   g_pi[NSLOT * B_T];

// ---------------------------------------------------------------------------
__device__ __forceinline__ uint32_t smem_u32(const void* p) {
    uint32_t a;
    asm("{ .reg .u64 t; cvta.to.shared.u64 t, %1; cvt.u32.u64 %0, t; }" : "=r"(a) : "l"(p));
    return a;
}
__device__ __forceinline__ void cpasync16(uint32_t dst, const void* src) {
    asm volatile("cp.async.cg.shared.global [%0], [%1], 16;" :: "r"(dst), "l"(src));
}
__device__ __forceinline__ void cp_commit() {
    asm volatile("cp.async.commit_group;" ::: "memory");
}
__device__ __forceinline__ void cp_wait0() {
    asm volatile("cp.async.wait_group 0;" ::: "memory");
}
__device__ __forceinline__ uint32_t lds32(uint32_t a) {
    uint32_t v; asm volatile("ld.shared.b32 %0, [%1];" : "=r"(v) : "r"(a)); return v;
}
__device__ __forceinline__ float4 lds128(uint32_t a) {
    float4 v;
    asm volatile("ld.shared.v4.f32 {%0,%1,%2,%3}, [%4];"
                 : "=f"(v.x), "=f"(v.y), "=f"(v.z), "=f"(v.w) : "r"(a));
    return v;
}
// m16n8k16 row.col bf16 -> f32 accumulate (sm_80+, valid on base sm_100)
__device__ __forceinline__ void mma16816(float* d, const uint32_t* a, uint32_t b0, uint32_t b1) {
    asm volatile(
        "mma.sync.aligned.m16n8k16.row.col.f32.bf16.bf16.f32 "
        "{%0,%1,%2,%3}, {%4,%5,%6,%7}, {%8,%9}, {%0,%1,%2,%3};"
        : "+f"(d[0]), "+f"(d[1]), "+f"(d[2]), "+f"(d[3])
        : "r"(a[0]), "r"(a[1]), "r"(a[2]), "r"(a[3]), "r"(b0), "r"(b1));
}

// ============================================================================
// Kernel 1: projection (fp32), warp-per-row; writes fp32 g_V AND bf16 3-split
// g_A.  Split groups per row: [v1,v1,v1,v2,v2,v3,v2,v3].
// ============================================================================
#define PS_STR 17
__global__ __launch_bounds__(256) void proj_split_kernel(const float* __restrict__ H,
                                                         const float* __restrict__ P) {
    __shared__ float Ps[D_IN * PS_STR];
    const int tid = threadIdx.x;
    for (int i = tid; i < D_IN * E_DIM; i += 256) {
        int d = i >> 4, e = i & 15;
        Ps[d * PS_STR + e] = P[i];
    }
    __syncthreads();

    const int warp = tid >> 5;
    const int lane = tid & 31;
    const int row  = blockIdx.x * 8 + warp;

    float acc[E_DIM];
#pragma unroll
    for (int e = 0; e < E_DIM; ++e) acc[e] = 0.0f;

    const float* h = H + (size_t)row * D_IN;
#pragma unroll
    for (int i = 0; i < 10; ++i) {
        float hv = h[i * 32 + lane];
        const float* p = &Ps[(i * 32 + lane) * PS_STR];
#pragma unroll
        for (int e = 0; e < E_DIM; ++e) acc[e] = fmaf(hv, p[e], acc[e]);
    }
#pragma unroll
    for (int off = 16; off >= 1; off >>= 1)
#pragma unroll
        for (int e = 0; e < E_DIM; ++e)
            acc[e] += __shfl_xor_sync(0xFFFFFFFFu, acc[e], off);

    if (lane < E_DIM) {
        float v = acc[lane];
        g_V[(size_t)row * E_DIM + lane] = v;
        __nv_bfloat16 b1 = __float2bfloat16(v);
        float r1 = v - __bfloat162float(b1);
        __nv_bfloat16 b2 = __float2bfloat16(r1);
        float r2 = r1 - __bfloat162float(b2);
        __nv_bfloat16 b3 = __float2bfloat16(r2);
        unsigned short s[3] = { __bfloat16_as_ushort(b1), __bfloat16_as_ushort(b2),
                                __bfloat16_as_ushort(b3) };
        const int ag[8] = {0, 0, 0, 1, 1, 2, 1, 2};
        unsigned short* dst = g_A + (size_t)row * 128 + lane;
#pragma unroll
        for (int g = 0; g < 8; ++g) dst[g * 16] = s[ag[g]];
    }
}

// ============================================================================
// Kernel 2: codebook bf16 3-split.  B groups: [c1,c2,c3,c1,c2,c1,c3,c2].
// ============================================================================
__global__ __launch_bounds__(256) void cb_split_kernel(const float* __restrict__ CB) {
    int r = blockIdx.x * 256 + threadIdx.x;
    if (r >= K_CB) return;
    unsigned short s[3][E_DIM];
#pragma unroll
    for (int e = 0; e < E_DIM; ++e) {
        float v = CB[(size_t)r * E_DIM + e];
        __nv_bfloat16 b1 = __float2bfloat16(v);
        float r1 = v - __bfloat162float(b1);
        __nv_bfloat16 b2 = __float2bfloat16(r1);
        float r2 = r1 - __bfloat162float(b2);
        __nv_bfloat16 b3 = __float2bfloat16(r2);
        s[0][e] = __bfloat16_as_ushort(b1);
        s[1][e] = __bfloat16_as_ushort(b2);
        s[2][e] = __bfloat16_as_ushort(b3);
    }
    const int bg[8] = {0, 1, 2, 0, 1, 0, 2, 1};
    ushort4* dst = (ushort4*)(g_Bs + (size_t)r * 128);
#pragma unroll
    for (int g = 0; g < 8; ++g)
#pragma unroll
        for (int q = 0; q < 4; ++q)
            dst[g * 4 + q] = make_ushort4(s[bg[g]][4 * q], s[bg[g]][4 * q + 1],
                                          s[bg[g]][4 * q + 2], s[bg[g]][4 * q + 3]);
}

// ============================================================================
// Kernel 3: DUAL-PIPE score.  Block = 8 warps, 64 rows, grid (250, 8 ksegs).
// Warps 0-3 (MMA, tensor pipe): cands [0,32) of each 64-tile, bf16-split HMMA.
// Warps 4-7 (FFMA, fma pipe):   cands [32,64), fp32 dot vs fp32 CB tile.
// wid%4 -> 1 MMA + 1 FFMA warp per SMSP per block.
// Smem: A stage (16KB) overlaid on the two 8KB Bm buffers; 2x2KB fp32 Bf.
// ============================================================================
#define SM_BM(b)  ((b) * 8192)             // bf16-split B tiles (also A stage)
#define SM_BF(b)  (16384 + (b) * 2048)     // fp32 CB tiles
#define SM_RED    20480                    // FFMA cross-warp reduce: 4*64*(4+4) B

__global__ __launch_bounds__(256) void score_kernel(const float* __restrict__ CBf) {
    __shared__ __align__(16) char smem[20480 + 4 * 64 * 8];
    const uint32_t sb = smem_u32(smem);
    const int tid  = threadIdx.x;
    const int lane = tid & 31;
    const int warp = tid >> 5;
    const int rb   = blockIdx.x * ROWS_PB;
    const int kseg = blockIdx.y;
    const int kb0  = kseg * CANDS;

    // ---- stage A (64 rows x 256B, swizzled) into the Bm region ----
#pragma unroll
    for (int i = 0; i < 4; ++i) {
        int idx = tid + i * 256;                 // 1024 units
        int row = idx >> 4, u = idx & 15;
        cpasync16(sb + row * 256 + (((u ^ (row & 7)) << 4)),
                  (const char*)g_A + (size_t)(rb + row) * 256 + u * 16);
    }
    cp_commit();
    cp_wait0();
    __syncthreads();

    // ---- per-role setup ----
    uint32_t a[8][4];                 // MMA: A fragments (rows warp*16+q, +8)
    float v0[16], v1[16];             // FFMA: two fp32 row vectors
    const int q  = lane >> 2;
    const int c4 = lane & 3;

    if (warp < 4) {
        int R0 = warp * 16 + q, R1 = R0 + 8;
        uint32_t b0 = sb + R0 * 256 + c4 * 4;
        uint32_t b1 = sb + R1 * 256 + c4 * 4;
        int x0 = R0 & 7, x1 = R1 & 7;
#pragma unroll
        for (int kk = 0; kk < 8; ++kk) {
            a[kk][0] = lds32(b0 + (((2 * kk)     ^ x0) << 4));
            a[kk][1] = lds32(b1 + (((2 * kk)     ^ x1) << 4));
            a[kk][2] = lds32(b0 + (((2 * kk + 1) ^ x0) << 4));
            a[kk][3] = lds32(b1 + (((2 * kk + 1) ^ x1) << 4));
        }
    } else {
        const float4* V0 = (const float4*)(g_V + (size_t)(rb + lane) * E_DIM);
        const float4* V1 = (const float4*)(g_V + (size_t)(rb + 32 + lane) * E_DIM);
#pragma unroll
        for (int j = 0; j < 4; ++j) {
            float4 x = V0[j];
            v0[4*j] = x.x; v0[4*j+1] = x.y; v0[4*j+2] = x.z; v0[4*j+3] = x.w;
            float4 y = V1[j];
            v1[4*j] = y.x; v1[4*j+1] = y.y; v1[4*j+2] = y.z; v1[4*j+3] = y.w;
        }
    }
    __syncthreads();      // A region free for B tiles

    // ---- stage tile 0 ----
    auto stageTile = [&](int t, int buf) {
        int cand0 = kb0 + t * NT;
        // Bm: 32 cands x 16 units, swizzled
#pragma unroll
        for (int i = 0; i < 2; ++i) {
            int idx = tid + i * 256;             // 512 units
            int row = idx >> 4, u = idx & 15;
            cpasync16(sb + SM_BM(buf) + row * 256 + ((u ^ (row & 7)) << 4),
                      (const char*)g_Bs + (size_t)(cand0 + row) * 256 + u * 16);
        }
        // Bf: 32 fp32 cands x 4 units, linear
        if (tid < 128) {
            int row = tid >> 2, u = tid & 3;
            cpasync16(sb + SM_BF(buf) + row * 64 + u * 16,
                      (const char*)CBf + (size_t)(cand0 + 32 + row) * 64 + u * 16);
        }
    };
    stageTile(0, 0);
    cp_commit();

    float best0 = __int_as_float(0xff800000), best1 = best0;
    int   bi0 = 0, bi1 = 0;

    for (int t = 0; t < TILES; ++t) {
        cp_wait0();
        __syncthreads();
        const int buf = t & 1;
        if (t + 1 < TILES) { stageTile(t + 1, buf ^ 1); cp_commit(); }

        if (warp < 4) {
            // ---- tensor pipe: 4 n-groups (32 cands), 4 independent chains ----
            float d[4][4] = {{0,0,0,0},{0,0,0,0},{0,0,0,0},{0,0,0,0}};
            uint32_t cb = sb + SM_BM(buf) + q * 256 + c4 * 4;
#pragma unroll
            for (int kk = 0; kk < 8; ++kk) {
                uint32_t o0 = ((2 * kk)     ^ q) << 4;
                uint32_t o1 = ((2 * kk + 1) ^ q) << 4;
#pragma unroll
                for (int g = 0; g < 4; ++g) {
                    uint32_t bb0 = lds32(cb + g * 2048 + o0);
                    uint32_t bb1 = lds32(cb + g * 2048 + o1);
                    mma16816(d[g], a[kk], bb0, bb1);
                }
            }
#pragma unroll
            for (int g = 0; g < 4; ++g) {       // ascending k
                const int kA = kb0 + t * NT + g * 8 + 2 * c4;
                if (d[g][0] > best0) { best0 = d[g][0]; bi0 = kA; }
                if (d[g][1] > best0) { best0 = d[g][1]; bi0 = kA + 1; }
                if (d[g][2] > best1) { best1 = d[g][2]; bi1 = kA; }
                if (d[g][3] > best1) { best1 = d[g][3]; bi1 = kA + 1; }
            }
        } else {
            // ---- fma pipe: 8 fp32 cands for this warp, 2 rows per lane ----
            const int coff = (warp - 4) * 8;
            uint32_t cb = sb + SM_BF(buf) + coff * 64;
#pragma unroll
            for (int j = 0; j < 8; ++j) {
                float4 c0 = lds128(cb + j * 64);
                float4 c1 = lds128(cb + j * 64 + 16);
                float4 c2 = lds128(cb + j * 64 + 32);
                float4 c3 = lds128(cb + j * 64 + 48);
                float t0 = c0.x*v0[0],  t1 = c0.y*v0[1],  t2 = c0.z*v0[2],  t3 = c0.w*v0[3];
                t0 = fmaf(c1.x, v0[4],  t0); t1 = fmaf(c1.y, v0[5],  t1);
                t2 = fmaf(c1.z, v0[6],  t2); t3 = fmaf(c1.w, v0[7],  t3);
                t0 = fmaf(c2.x, v0[8],  t0); t1 = fmaf(c2.y, v0[9],  t1);
                t2 = fmaf(c2.z, v0[10], t2); t3 = fmaf(c2.w, v0[11], t3);
                t0 = fmaf(c3.x, v0[12], t0); t1 = fmaf(c3.y, v0[13], t1);
                t2 = fmaf(c3.z, v0[14], t2); t3 = fmaf(c3.w, v0[15], t3);
                float s0 = (t0 + t1) + (t2 + t3);
                float u0 = c0.x*v1[0],  u1 = c0.y*v1[1],  u2 = c0.z*v1[2],  u3 = c0.w*v1[3];
                u0 = fmaf(c1.x, v1[4],  u0); u1 = fmaf(c1.y, v1[5],  u1);
                u2 = fmaf(c1.z, v1[6],  u2); u3 = fmaf(c1.w, v1[7],  u3);
                u0 = fmaf(c2.x, v1[8],  u0); u1 = fmaf(c2.y, v1[9],  u1);
                u2 = fmaf(c2.z, v1[10], u2); u3 = fmaf(c2.w, v1[11], u3);
                u0 = fmaf(c3.x, v1[12], u0); u1 = fmaf(c3.y, v1[13], u1);
                u2 = fmaf(c3.z, v1[14], u2); u3 = fmaf(c3.w, v1[15], u3);
                float s1 = (u0 + u1) + (u2 + u3);
                int k = kb0 + t * NT + 32 + coff + j;
                if (s0 > best0) { best0 = s0; bi0 = k; }
                if (s1 > best1) { best1 = s1; bi1 = k; }
            }
        }
        __syncthreads();
    }

    // ---- write partials ----
    if (warp < 4) {
        // reduce over the 4 quad lanes (same rows, disjoint n-residues)
#pragma unroll
        for (int off = 1; off <= 2; off <<= 1) {
            float ov = __shfl_xor_sync(0xFFFFFFFFu, best0, off);
            int   oi = __shfl_xor_sync(0xFFFFFFFFu, bi0,   off);
            if (ov > best0 || (ov == best0 && oi < bi0)) { best0 = ov; bi0 = oi; }
            ov = __shfl_xor_sync(0xFFFFFFFFu, best1, off);
            oi = __shfl_xor_sync(0xFFFFFFFFu, bi1,   off);
            if (ov > best1 || (ov == best1 && oi < bi1)) { best1 = ov; bi1 = oi; }
        }
        if (c4 == 0) {
            int r0 = warp * 16 + q;
            g_pv[(size_t)kseg * B_T + rb + r0] = best0;
            g_pi[(size_t)kseg * B_T + rb + r0] = bi0;
            g_pv[(size_t)kseg * B_T + rb + r0 + 8] = best1;
            g_pi[(size_t)kseg * B_T + rb + r0 + 8] = bi1;
        }
    } else {
        // cross-warp reduce (warps 4-7 hold same rows, disjoint cand ranges)
        float* rv = (float*)(smem + SM_RED);
        int*   ri = (int*)(smem + SM_RED + 4 * 64 * 4);
        int w = warp - 4;
        rv[w * 64 + lane]      = best0;  ri[w * 64 + lane]      = bi0;
        rv[w * 64 + 32 + lane] = best1;  ri[w * 64 + 32 + lane] = bi1;
    }
    __syncthreads();
    if (warp >= 4) {
        const float* rv = (const float*)(smem + SM_RED);
        const int*   ri = (const int*)(smem + SM_RED + 4 * 64 * 4);
        if (warp == 4) {
#pragma unroll
            for (int half = 0; half < 2; ++half) {
                int r = half * 32 + lane;
                float bv = rv[r]; int bi = ri[r];
#pragma unroll
                for (int w = 1; w < 4; ++w) {
                    float vv = rv[w * 64 + r]; int ii = ri[w * 64 + r];
                    if (vv > bv || (vv == bv && ii < bi)) { bv = vv; bi = ii; }
                }
                g_pv[(size_t)(KS2 + kseg) * B_T + rb + r] = bv;
                g_pi[(size_t)(KS2 + kseg) * B_T + rb + r] = bi;
            }
        }
    }
}

// ============================================================================
// Kernel 4: combine all NSLOT partials; label as float VALUE (float32 output).
// ============================================================================
__global__ __launch_bounds__(256) void combine_kernel(float* __restrict__ out) {
    int row = blockIdx.x * 256 + threadIdx.x;
    if (row >= B_T) return;
    float bv = g_pv[row];
    int   bi = g_pi[row];
#pragma unroll
    for (int s = 1; s < NSLOT; ++s) {
        float v = g_pv[(size_t)s * B_T + row];
        int   i = g_pi[(size_t)s * B_T + row];
        if (v > bv || (v == bv && i < bi)) { bv = v; bi = i; }
    }
    out[row] = (float)bi;
}

// ============================================================================
extern "C" void kernel_launch(void* const* d_in, const int* in_sizes, int n_in,
                              void* d_out, int out_size) {
    // Input dispatch by element count (ordering-proof):
    //   H = 5,120,000 ; P = 5,120 ; CB = 131,072
    const float* H  = nullptr;
    const float* P  = nullptr;
    const float* CB = nullptr;
    for (int i = 0; i < n_in; ++i) {
        if      (in_sizes[i] == B_T * D_IN)   H  = (const float*)d_in[i];
        else if (in_sizes[i] == D_IN * E_DIM) P  = (const float*)d_in[i];
        else if (in_sizes[i] == K_CB * E_DIM) CB = (const float*)d_in[i];
    }
    if (!H)  H  = (const float*)d_in[0];
    if (!P)  P  = (const float*)d_in[1];
    if (!CB) CB = (const float*)d_in[2];

    float* out = (float*)d_out;

    proj_split_kernel<<<B_T / 8, 256>>>(H, P);
    cb_split_kernel<<<K_CB / 256, 256>>>(CB);
    score_kernel<<<dim3(GRID_R, KS2), 256>>>(CB);
    combine_kernel<<<(B_T + 255) / 256, 256>>>(out);
}

// round 10
// speedup vs baseline: 1.2354x; 1.0717x over previous
#include <cuda_runtime.h>
#include <cuda_bf16.h>
#include <cstdint>

#define B_T    16000
#define D_IN   320
#define E_DIM  16
#define K_CB   8192
#define KS2    8
#define CANDS  (K_CB / KS2)        // 1024 cands per kseg
#define NT     128                 // cands per tile (64 MMA + 64 FFMA)
#define TILES  (CANDS / NT)        // 8
#define ROWS_PB 64
#define GRID_R (B_T / ROWS_PB)     // 250
#define NSLOT  (2 * KS2)

// ---- scratch (device globals: the sanctioned no-alloc path) ----
__device__ __align__(16) unsigned short g_A[B_T * 128];    // bf16 split-A (K=128), 4 MB
__device__ __align__(16) unsigned short g_Bs[K_CB * 128];  // bf16 split-B, 2 MB
__device__ __align__(16) float g_V[B_T * E_DIM];           // fp32 projected rows, 1 MB
__device__ float g_pv[NSLOT * B_T];
__device__ int   g_pi[NSLOT * B_T];

// ---------------------------------------------------------------------------
__device__ __forceinline__ uint32_t smem_u32(const void* p) {
    uint32_t a;
    asm("{ .reg .u64 t; cvta.to.shared.u64 t, %1; cvt.u32.u64 %0, t; }" : "=r"(a) : "l"(p));
    return a;
}
__device__ __forceinline__ void cpasync16(uint32_t dst, const void* src) {
    asm volatile("cp.async.cg.shared.global [%0], [%1], 16;" :: "r"(dst), "l"(src));
}
__device__ __forceinline__ void cp_commit() {
    asm volatile("cp.async.commit_group;" ::: "memory");
}
__device__ __forceinline__ void cp_wait0() {
    asm volatile("cp.async.wait_group 0;" ::: "memory");
}
__device__ __forceinline__ uint32_t lds32(uint32_t a) {
    uint32_t v; asm volatile("ld.shared.b32 %0, [%1];" : "=r"(v) : "r"(a)); return v;
}
__device__ __forceinline__ float4 lds128(uint32_t a) {
    float4 v;
    asm volatile("ld.shared.v4.f32 {%0,%1,%2,%3}, [%4];"
                 : "=f"(v.x), "=f"(v.y), "=f"(v.z), "=f"(v.w) : "r"(a));
    return v;
}
// m16n8k16 row.col bf16 -> f32 accumulate
__device__ __forceinline__ void mma16816(float* d, const uint32_t* a, uint32_t b0, uint32_t b1) {
    asm volatile(
        "mma.sync.aligned.m16n8k16.row.col.f32.bf16.bf16.f32 "
        "{%0,%1,%2,%3}, {%4,%5,%6,%7}, {%8,%9}, {%0,%1,%2,%3};"
        : "+f"(d[0]), "+f"(d[1]), "+f"(d[2]), "+f"(d[3])
        : "r"(a[0]), "r"(a[1]), "r"(a[2]), "r"(a[3]), "r"(b0), "r"(b1));
}

// ============================================================================
// Kernel 1: projection (fp32), warp-per-row; writes fp32 g_V AND bf16 3-split
// g_A.  Split groups per row: [v1,v1,v1,v2,v2,v3,v2,v3].
// ============================================================================
#define PS_STR 17
__global__ __launch_bounds__(256) void proj_split_kernel(const float* __restrict__ H,
                                                         const float* __restrict__ P) {
    __shared__ float Ps[D_IN * PS_STR];
    const int tid = threadIdx.x;
    for (int i = tid; i < D_IN * E_DIM; i += 256) {
        int d = i >> 4, e = i & 15;
        Ps[d * PS_STR + e] = P[i];
    }
    __syncthreads();

    const int warp = tid >> 5;
    const int lane = tid & 31;
    const int row  = blockIdx.x * 8 + warp;

    float acc[E_DIM];
#pragma unroll
    for (int e = 0; e < E_DIM; ++e) acc[e] = 0.0f;

    const float* h = H + (size_t)row * D_IN;
#pragma unroll
    for (int i = 0; i < 10; ++i) {
        float hv = h[i * 32 + lane];
        const float* p = &Ps[(i * 32 + lane) * PS_STR];
#pragma unroll
        for (int e = 0; e < E_DIM; ++e) acc[e] = fmaf(hv, p[e], acc[e]);
    }
#pragma unroll
    for (int off = 16; off >= 1; off >>= 1)
#pragma unroll
        for (int e = 0; e < E_DIM; ++e)
            acc[e] += __shfl_xor_sync(0xFFFFFFFFu, acc[e], off);

    if (lane < E_DIM) {
        float v = acc[lane];
        g_V[(size_t)row * E_DIM + lane] = v;
        __nv_bfloat16 b1 = __float2bfloat16(v);
        float r1 = v - __bfloat162float(b1);
        __nv_bfloat16 b2 = __float2bfloat16(r1);
        float r2 = r1 - __bfloat162float(b2);
        __nv_bfloat16 b3 = __float2bfloat16(r2);
        unsigned short s[3] = { __bfloat16_as_ushort(b1), __bfloat16_as_ushort(b2),
                                __bfloat16_as_ushort(b3) };
        const int ag[8] = {0, 0, 0, 1, 1, 2, 1, 2};
        unsigned short* dst = g_A + (size_t)row * 128 + lane;
#pragma unroll
        for (int g = 0; g < 8; ++g) dst[g * 16] = s[ag[g]];
    }
}

// ============================================================================
// Kernel 2: codebook bf16 3-split.  B groups: [c1,c2,c3,c1,c2,c1,c3,c2].
// ============================================================================
__global__ __launch_bounds__(256) void cb_split_kernel(const float* __restrict__ CB) {
    int r = blockIdx.x * 256 + threadIdx.x;
    if (r >= K_CB) return;
    unsigned short s[3][E_DIM];
#pragma unroll
    for (int e = 0; e < E_DIM; ++e) {
        float v = CB[(size_t)r * E_DIM + e];
        __nv_bfloat16 b1 = __float2bfloat16(v);
        float r1 = v - __bfloat162float(b1);
        __nv_bfloat16 b2 = __float2bfloat16(r1);
        float r2 = r1 - __bfloat162float(b2);
        __nv_bfloat16 b3 = __float2bfloat16(r2);
        s[0][e] = __bfloat16_as_ushort(b1);
        s[1][e] = __bfloat16_as_ushort(b2);
        s[2][e] = __bfloat16_as_ushort(b3);
    }
    const int bg[8] = {0, 1, 2, 0, 1, 0, 2, 1};
    ushort4* dst = (ushort4*)(g_Bs + (size_t)r * 128);
#pragma unroll
    for (int g = 0; g < 8; ++g)
#pragma unroll
        for (int q = 0; q < 4; ++q)
            dst[g * 4 + q] = make_ushort4(s[bg[g]][4 * q], s[bg[g]][4 * q + 1],
                                          s[bg[g]][4 * q + 2], s[bg[g]][4 * q + 3]);
}

// ============================================================================
// Kernel 3: DUAL-PIPE score, low-overhead version.
// Block = 8 warps, 64 rows, grid (250, 8).  Tile = 128 cands (64 MMA + 64 FFMA),
// only 8 tiles -> half the barriers of round 9.  3 blocks/SM.
// ============================================================================
#define SM_BM(b)  ((b) * 16384)            // bf16-split B tiles (buf0 doubles as A stage)
#define SM_BF(b)  (32768 + (b) * 4096)     // fp32 CB tiles
#define SM_RED    40960

__global__ __launch_bounds__(256, 3) void score_kernel(const float* __restrict__ CBf) {
    __shared__ __align__(16) char smem[40960 + 2048];
    const uint32_t sb = smem_u32(smem);
    const int tid  = threadIdx.x;
    const int lane = tid & 31;
    const int warp = tid >> 5;
    const int rb   = blockIdx.x * ROWS_PB;
    const int kseg = blockIdx.y;
    const int kb0  = kseg * CANDS;

    // ---- stage A (64 rows x 256B, swizzled) into Bm buf0 ----
#pragma unroll
    for (int i = 0; i < 4; ++i) {
        int idx = tid + i * 256;
        int row = idx >> 4, u = idx & 15;
        cpasync16(sb + row * 256 + ((u ^ (row & 7)) << 4),
                  (const char*)g_A + (size_t)(rb + row) * 256 + u * 16);
    }
    cp_commit();
    cp_wait0();
    __syncthreads();

    uint32_t a[8][4];
    float v0[16], v1[16];
    const int q  = lane >> 2;
    const int c4 = lane & 3;

    if (warp < 4) {
        int R0 = warp * 16 + q, R1 = R0 + 8;
        uint32_t b0 = sb + R0 * 256 + c4 * 4;
        uint32_t b1 = sb + R1 * 256 + c4 * 4;
        int x0 = R0 & 7, x1 = R1 & 7;
#pragma unroll
        for (int kk = 0; kk < 8; ++kk) {
            a[kk][0] = lds32(b0 + (((2 * kk)     ^ x0) << 4));
            a[kk][1] = lds32(b1 + (((2 * kk)     ^ x1) << 4));
            a[kk][2] = lds32(b0 + (((2 * kk + 1) ^ x0) << 4));
            a[kk][3] = lds32(b1 + (((2 * kk + 1) ^ x1) << 4));
        }
    } else {
        const float4* V0 = (const float4*)(g_V + (size_t)(rb + lane) * E_DIM);
        const float4* V1 = (const float4*)(g_V + (size_t)(rb + 32 + lane) * E_DIM);
#pragma unroll
        for (int j = 0; j < 4; ++j) {
            float4 x = V0[j];
            v0[4*j] = x.x; v0[4*j+1] = x.y; v0[4*j+2] = x.z; v0[4*j+3] = x.w;
            float4 y = V1[j];
            v1[4*j] = y.x; v1[4*j+1] = y.y; v1[4*j+2] = y.z; v1[4*j+3] = y.w;
        }
    }
    __syncthreads();

    auto stageTile = [&](int t, int buf) {
        int cand0 = kb0 + t * NT;
        // Bm: 64 cands x 16 units, swizzled
#pragma unroll
        for (int i = 0; i < 4; ++i) {
            int idx = tid + i * 256;
            int row = idx >> 4, u = idx & 15;
            cpasync16(sb + SM_BM(buf) + row * 256 + ((u ^ (row & 7)) << 4),
                      (const char*)g_Bs + (size_t)(cand0 + row) * 256 + u * 16);
        }
        // Bf: 64 fp32 cands x 4 units, linear
        {
            int row = tid >> 2, u = tid & 3;
            cpasync16(sb + SM_BF(buf) + row * 64 + u * 16,
                      (const char*)CBf + (size_t)(cand0 + 64 + row) * 64 + u * 16);
        }
    };
    stageTile(0, 0);
    cp_commit();

    float best0 = __int_as_float(0xff800000), best1 = best0;
    int   bi0 = 0, bi1 = 0;

    for (int t = 0; t < TILES; ++t) {
        cp_wait0();
        __syncthreads();
        const int buf = t & 1;
        if (t + 1 < TILES) { stageTile(t + 1, buf ^ 1); cp_commit(); }

        if (warp < 4) {
            // ---- tensor pipe: 64 cands in two passes of 4 independent chains ----
#pragma unroll
            for (int pass = 0; pass < 2; ++pass) {
                float d[4][4] = {{0,0,0,0},{0,0,0,0},{0,0,0,0},{0,0,0,0}};
                uint32_t cb = sb + SM_BM(buf) + (pass * 32 + q) * 256 + c4 * 4;
#pragma unroll
                for (int kk = 0; kk < 8; ++kk) {
                    uint32_t o0 = ((2 * kk)     ^ q) << 4;
                    uint32_t o1 = ((2 * kk + 1) ^ q) << 4;
#pragma unroll
                    for (int g = 0; g < 4; ++g) {
                        uint32_t bb0 = lds32(cb + g * 2048 + o0);
                        uint32_t bb1 = lds32(cb + g * 2048 + o1);
                        mma16816(d[g], a[kk], bb0, bb1);
                    }
                }
#pragma unroll
                for (int g = 0; g < 4; ++g) {   // ascending k
                    const int kA = kb0 + t * NT + pass * 32 + g * 8 + 2 * c4;
                    if (d[g][0] > best0) { best0 = d[g][0]; bi0 = kA; }
                    if (d[g][1] > best0) { best0 = d[g][1]; bi0 = kA + 1; }
                    if (d[g][2] > best1) { best1 = d[g][2]; bi1 = kA; }
                    if (d[g][3] > best1) { best1 = d[g][3]; bi1 = kA + 1; }
                }
            }
        } else {
            // ---- fma pipe: 16 fp32 cands for this warp, 2 rows per lane ----
            const int coff = (warp - 4) * 16;
            uint32_t cb = sb + SM_BF(buf) + coff * 64;
#pragma unroll
            for (int j = 0; j < 16; ++j) {
                float4 c0 = lds128(cb + j * 64);
                float4 c1 = lds128(cb + j * 64 + 16);
                float4 c2 = lds128(cb + j * 64 + 32);
                float4 c3 = lds128(cb + j * 64 + 48);
                float t0 = c0.x * v0[0], t1 = c0.y * v0[1];
                t0 = fmaf(c0.z, v0[2],  t0); t1 = fmaf(c0.w, v0[3],  t1);
                t0 = fmaf(c1.x, v0[4],  t0); t1 = fmaf(c1.y, v0[5],  t1);
                t0 = fmaf(c1.z, v0[6],  t0); t1 = fmaf(c1.w, v0[7],  t1);
                t0 = fmaf(c2.x, v0[8],  t0); t1 = fmaf(c2.y, v0[9],  t1);
                t0 = fmaf(c2.z, v0[10], t0); t1 = fmaf(c2.w, v0[11], t1);
                t0 = fmaf(c3.x, v0[12], t0); t1 = fmaf(c3.y, v0[13], t1);
                t0 = fmaf(c3.z, v0[14], t0); t1 = fmaf(c3.w, v0[15], t1);
                float s0 = t0 + t1;
                float u0 = c0.x * v1[0], u1 = c0.y * v1[1];
                u0 = fmaf(c0.z, v1[2],  u0); u1 = fmaf(c0.w, v1[3],  u1);
                u0 = fmaf(c1.x, v1[4],  u0); u1 = fmaf(c1.y, v1[5],  u1);
                u0 = fmaf(c1.z, v1[6],  u0); u1 = fmaf(c1.w, v1[7],  u1);
                u0 = fmaf(c2.x, v1[8],  u0); u1 = fmaf(c2.y, v1[9],  u1);
                u0 = fmaf(c2.z, v1[10], u0); u1 = fmaf(c2.w, v1[11], u1);
                u0 = fmaf(c3.x, v1[12], u0); u1 = fmaf(c3.y, v1[13], u1);
                u0 = fmaf(c3.z, v1[14], u0); u1 = fmaf(c3.w, v1[15], u1);
                float s1 = u0 + u1;
                int k = kb0 + t * NT + 64 + coff + j;
                if (s0 > best0) { best0 = s0; bi0 = k; }
                if (s1 > best1) { best1 = s1; bi1 = k; }
            }
        }
        __syncthreads();
    }

    // ---- write partials ----
    if (warp < 4) {
#pragma unroll
        for (int off = 1; off <= 2; off <<= 1) {
            float ov = __shfl_xor_sync(0xFFFFFFFFu, best0, off);
            int   oi = __shfl_xor_sync(0xFFFFFFFFu, bi0,   off);
            if (ov > best0 || (ov == best0 && oi < bi0)) { best0 = ov; bi0 = oi; }
            ov = __shfl_xor_sync(0xFFFFFFFFu, best1, off);
            oi = __shfl_xor_sync(0xFFFFFFFFu, bi1,   off);
            if (ov > best1 || (ov == best1 && oi < bi1)) { best1 = ov; bi1 = oi; }
        }
        if (c4 == 0) {
            int r0 = warp * 16 + q;
            g_pv[(size_t)kseg * B_T + rb + r0] = best0;
            g_pi[(size_t)kseg * B_T + rb + r0] = bi0;
            g_pv[(size_t)kseg * B_T + rb + r0 + 8] = best1;
            g_pi[(size_t)kseg * B_T + rb + r0 + 8] = bi1;
        }
    } else {
        float* rv = (float*)(smem + SM_RED);
        int*   ri = (int*)(smem + SM_RED + 4 * 64 * 4);
        int w = warp - 4;
        rv[w * 64 + lane]      = best0;  ri[w * 64 + lane]      = bi0;
        rv[w * 64 + 32 + lane] = best1;  ri[w * 64 + 32 + lane] = bi1;
    }
    __syncthreads();
    if (warp == 4) {
        const float* rv = (const float*)(smem + SM_RED);
        const int*   ri = (const int*)(smem + SM_RED + 4 * 64 * 4);
#pragma unroll
        for (int half = 0; half < 2; ++half) {
            int r = half * 32 + lane;
            float bv = rv[r]; int bi = ri[r];
#pragma unroll
            for (int w = 1; w < 4; ++w) {
                float vv = rv[w * 64 + r]; int ii = ri[w * 64 + r];
                if (vv > bv || (vv == bv && ii < bi)) { bv = vv; bi = ii; }
            }
            g_pv[(size_t)(KS2 + kseg) * B_T + rb + r] = bv;
            g_pi[(size_t)(KS2 + kseg) * B_T + rb + r] = bi;
        }
    }
}

// ============================================================================
// Kernel 4: combine all NSLOT partials; label as float VALUE (float32 output).
// ============================================================================
__global__ __launch_bounds__(256) void combine_kernel(float* __restrict__ out) {
    int row = blockIdx.x * 256 + threadIdx.x;
    if (row >= B_T) return;
    float bv = g_pv[row];
    int   bi = g_pi[row];
#pragma unroll
    for (int s = 1; s < NSLOT; ++s) {
        float v = g_pv[(size_t)s * B_T + row];
        int   i = g_pi[(size_t)s * B_T + row];
        if (v > bv || (v == bv && i < bi)) { bv = v; bi = i; }
    }
    out[row] = (float)bi;
}

// ============================================================================
extern "C" void kernel_launch(void* const* d_in, const int* in_sizes, int n_in,
                              void* d_out, int out_size) {
    const float* H  = nullptr;
    const float* P  = nullptr;
    const float* CB = nullptr;
    for (int i = 0; i < n_in; ++i) {
        if      (in_sizes[i] == B_T * D_IN)   H  = (const float*)d_in[i];
        else if (in_sizes[i] == D_IN * E_DIM) P  = (const float*)d_in[i];
        else if (in_sizes[i] == K_CB * E_DIM) CB = (const float*)d_in[i];
    }
    if (!H)  H  = (const float*)d_in[0];
    if (!P)  P  = (const float*)d_in[1];
    if (!CB) CB = (const float*)d_in[2];

    float* out = (float*)d_out;

    proj_split_kernel<<<B_T / 8, 256>>>(H, P);
    cb_split_kernel<<<K_CB / 256, 256>>>(CB);
    score_kernel<<<dim3(GRID_R, KS2), 256>>>(CB);
    combine_kernel<<<(B_T + 255) / 256, 256>>>(out);
}

// round 11
// speedup vs baseline: 1.4392x; 1.1650x over previous
#include <cuda_runtime.h>
#include <cuda_bf16.h>
#include <cstdint>

#define B_T    16000
#define D_IN   320
#define E_DIM  16
#define K_CB   8192
#define ROWS_PB 128
#define GRID_R (B_T / ROWS_PB)     // 125 blocks, each owns 128 rows x all cands
#define TC     128                 // cands per smem tile
#define NTILE  (K_CB / TC)         // 64
#define DELTA  2e-4f               // >= 2.6x the 7.6e-5 approx two-dot error bound

// ---- scratch (device globals: the sanctioned no-alloc path) ----
__device__ __align__(16) unsigned short g_Ak[B_T * 64];   // [v1,v2,v1,0] x16 bf16, 2 MB
__device__ __align__(16) unsigned short g_Bk[K_CB * 64];  // [c1,c1,c2,0] x16 bf16, 1 MB
__device__ __align__(16) float g_V[B_T * E_DIM];          // raw fp32 rows, 1 MB
__device__ int g_dirty_n;
__device__ int g_dirty[B_T];

// ---------------------------------------------------------------------------
__device__ __forceinline__ uint32_t smem_u32(const void* p) {
    uint32_t a;
    asm("{ .reg .u64 t; cvta.to.shared.u64 t, %1; cvt.u32.u64 %0, t; }" : "=r"(a) : "l"(p));
    return a;
}
__device__ __forceinline__ void cpasync16(uint32_t dst, const void* src) {
    asm volatile("cp.async.cg.shared.global [%0], [%1], 16;" :: "r"(dst), "l"(src));
}
__device__ __forceinline__ void cp_commit() {
    asm volatile("cp.async.commit_group;" ::: "memory");
}
__device__ __forceinline__ void cp_wait0() {
    asm volatile("cp.async.wait_group 0;" ::: "memory");
}
__device__ __forceinline__ uint32_t lds32(uint32_t a) {
    uint32_t v; asm volatile("ld.shared.b32 %0, [%1];" : "=r"(v) : "r"(a)); return v;
}
__device__ __forceinline__ void mma16816(float* d, const uint32_t* a, uint32_t b0, uint32_t b1) {
    asm volatile(
        "mma.sync.aligned.m16n8k16.row.col.f32.bf16.bf16.f32 "
        "{%0,%1,%2,%3}, {%4,%5,%6,%7}, {%8,%9}, {%0,%1,%2,%3};"
        : "+f"(d[0]), "+f"(d[1]), "+f"(d[2]), "+f"(d[3])
        : "r"(a[0]), "r"(a[1]), "r"(a[2]), "r"(a[3]), "r"(b0), "r"(b1));
}

// ============================================================================
// Kernel 1: projection (fp32, warp-per-row).  Writes raw fp32 g_V AND the
// 2.5-digit NORMALIZED bf16 split g_Ak = [v1, v2, v1, 0] (v-hat = v/||v||2).
// ============================================================================
#define PS_STR 17
__global__ __launch_bounds__(256) void proj_split_kernel(const float* __restrict__ H,
                                                         const float* __restrict__ P) {
    __shared__ float Ps[D_IN * PS_STR];
    const int tid = threadIdx.x;
    for (int i = tid; i < D_IN * E_DIM; i += 256) {
        int d = i >> 4, e = i & 15;
        Ps[d * PS_STR + e] = P[i];
    }
    __syncthreads();

    const int warp = tid >> 5;
    const int lane = tid & 31;
    const int row  = blockIdx.x * 8 + warp;

    float acc[E_DIM];
#pragma unroll
    for (int e = 0; e < E_DIM; ++e) acc[e] = 0.0f;

    const float* h = H + (size_t)row * D_IN;
#pragma unroll
    for (int i = 0; i < 10; ++i) {
        float hv = h[i * 32 + lane];
        const float* p = &Ps[(i * 32 + lane) * PS_STR];
#pragma unroll
        for (int e = 0; e < E_DIM; ++e) acc[e] = fmaf(hv, p[e], acc[e]);
    }
#pragma unroll
    for (int off = 16; off >= 1; off >>= 1)
#pragma unroll
        for (int e = 0; e < E_DIM; ++e)
            acc[e] += __shfl_xor_sync(0xFFFFFFFFu, acc[e], off);

    if (lane < E_DIM) {
        float n2 = 0.0f;
#pragma unroll
        for (int e = 0; e < E_DIM; ++e) n2 = fmaf(acc[e], acc[e], n2);
        float inv = rsqrtf(fmaxf(n2, 1e-30f));

        g_V[(size_t)row * E_DIM + lane] = acc[lane];

        float vh = acc[lane] * inv;
        __nv_bfloat16 b1 = __float2bfloat16(vh);
        float r1 = vh - __bfloat162float(b1);
        __nv_bfloat16 b2 = __float2bfloat16(r1);
        unsigned short* dst = g_Ak + (size_t)row * 64;
        dst[lane]      = __bfloat16_as_ushort(b1);
        dst[16 + lane] = __bfloat16_as_ushort(b2);
        dst[32 + lane] = __bfloat16_as_ushort(b1);
        dst[48 + lane] = 0;
    }
}

// ============================================================================
// Kernel 2: codebook 2-digit bf16 split [c1, c1, c2, 0] (CB rows already unit).
// Also resets the dirty-row counter (runs before score every graph replay).
// ============================================================================
__global__ __launch_bounds__(256) void cb_split_kernel(const float* __restrict__ CB) {
    if (blockIdx.x == 0 && threadIdx.x == 0) g_dirty_n = 0;
    int r = blockIdx.x * 256 + threadIdx.x;
    if (r >= K_CB) return;
    unsigned short* dst = g_Bk + (size_t)r * 64;
#pragma unroll
    for (int e = 0; e < E_DIM; ++e) {
        float v = CB[(size_t)r * E_DIM + e];
        __nv_bfloat16 c1 = __float2bfloat16(v);
        float r1 = v - __bfloat162float(c1);
        __nv_bfloat16 c2 = __float2bfloat16(r1);
        dst[e]      = __bfloat16_as_ushort(c1);
        dst[16 + e] = __bfloat16_as_ushort(c1);
        dst[32 + e] = __bfloat16_as_ushort(c2);
        dst[48 + e] = 0;
    }
}

// ============================================================================
// Kernel 3: approx HMMA score (K=48) + (best, idx, second) tracking.
// grid 125, block 256 (8 warps x 16 rows).  Clean rows (gap >= DELTA) write
// their label directly; near-tie rows go to the dirty list.
// ============================================================================
#define SM_A  0
#define SM_B0 16384
#define SM_B1 32768

__global__ __launch_bounds__(256) void score_kernel(float* __restrict__ out) {
    __shared__ __align__(16) char smem[49152];
    const uint32_t sb = smem_u32(smem);
    const int tid  = threadIdx.x;
    const int lane = tid & 31;
    const int warp = tid >> 5;
    const int rb   = blockIdx.x * ROWS_PB;
    const int q    = lane >> 2;
    const int c4   = lane & 3;

    // stage A (128 rows x 128B, unit-swizzled) and B tile 0
#pragma unroll
    for (int i = 0; i < 4; ++i) {
        int idx = tid + i * 256;
        int row = idx >> 3, u = idx & 7;
        cpasync16(sb + SM_A + row * 128 + ((u ^ (row & 7)) << 4),
                  (const char*)g_Ak + (size_t)(rb + row) * 128 + u * 16);
    }
#pragma unroll
    for (int i = 0; i < 4; ++i) {
        int idx = tid + i * 256;
        int row = idx >> 3, u = idx & 7;
        cpasync16(sb + SM_B0 + row * 128 + ((u ^ (row & 7)) << 4),
                  (const char*)g_Bk + (size_t)row * 128 + u * 16);
    }
    cp_commit();
    cp_wait0();
    __syncthreads();

    // A fragments (validated mapping): rows R0 = warp*16+q, R1 = R0+8
    uint32_t a[3][4];
    {
        int R0 = warp * 16 + q, R1 = R0 + 8;
        uint32_t base0 = sb + SM_A + R0 * 128 + c4 * 4;
        uint32_t base1 = sb + SM_A + R1 * 128 + c4 * 4;
        int x0 = R0 & 7, x1 = R1 & 7;
#pragma unroll
        for (int kk = 0; kk < 3; ++kk) {
            a[kk][0] = lds32(base0 + (((2 * kk)     ^ x0) << 4));
            a[kk][1] = lds32(base1 + (((2 * kk)     ^ x1) << 4));
            a[kk][2] = lds32(base0 + (((2 * kk + 1) ^ x0) << 4));
            a[kk][3] = lds32(base1 + (((2 * kk + 1) ^ x1) << 4));
        }
    }

    float best0 = __int_as_float(0xff800000), sec0 = best0;
    float best1 = __int_as_float(0xff800000), sec1 = best1;
    int bi0 = 0, bi1 = 0;

    for (int t = 0; t < NTILE; ++t) {
        cp_wait0();
        __syncthreads();
        const uint32_t buf = sb + ((t & 1) ? SM_B1 : SM_B0);
        if (t + 1 < NTILE) {
            const uint32_t nb = sb + (((t + 1) & 1) ? SM_B1 : SM_B0);
            int cand0 = (t + 1) * TC;
#pragma unroll
            for (int i = 0; i < 4; ++i) {
                int idx = tid + i * 256;
                int row = idx >> 3, u = idx & 7;
                cpasync16(nb + row * 128 + ((u ^ (row & 7)) << 4),
                          (const char*)g_Bk + (size_t)(cand0 + row) * 128 + u * 16);
            }
            cp_commit();
        }

        // 16 n-groups, processed in pairs (2 independent HMMA chains)
#pragma unroll 2
        for (int gg = 0; gg < 8; ++gg) {
            const int g0 = 2 * gg, g1 = 2 * gg + 1;
            float d0[4] = {0.f, 0.f, 0.f, 0.f};
            float d1[4] = {0.f, 0.f, 0.f, 0.f};
            uint32_t cb0 = buf + (g0 * 8 + q) * 128 + c4 * 4;
            uint32_t cb1 = buf + (g1 * 8 + q) * 128 + c4 * 4;
#pragma unroll
            for (int kk = 0; kk < 3; ++kk) {
                uint32_t o0 = ((2 * kk)     ^ q) << 4;
                uint32_t o1 = ((2 * kk + 1) ^ q) << 4;
                uint32_t b00 = lds32(cb0 + o0), b01 = lds32(cb0 + o1);
                uint32_t b10 = lds32(cb1 + o0), b11 = lds32(cb1 + o1);
                mma16816(d0, a[kk], b00, b01);
                mma16816(d1, a[kk], b10, b11);
            }
            const int k0 = t * TC + g0 * 8 + 2 * c4;    // g1 cands = k0+8, k0+9
            // row slot 0 (row R0), ascending k, strict > = first-max
            if (d0[0] > best0) { sec0 = best0; best0 = d0[0]; bi0 = k0; }     else sec0 = fmaxf(sec0, d0[0]);
            if (d0[1] > best0) { sec0 = best0; best0 = d0[1]; bi0 = k0 + 1; } else sec0 = fmaxf(sec0, d0[1]);
            if (d1[0] > best0) { sec0 = best0; best0 = d1[0]; bi0 = k0 + 8; } else sec0 = fmaxf(sec0, d1[0]);
            if (d1[1] > best0) { sec0 = best0; best0 = d1[1]; bi0 = k0 + 9; } else sec0 = fmaxf(sec0, d1[1]);
            // row slot 1 (row R1)
            if (d0[2] > best1) { sec1 = best1; best1 = d0[2]; bi1 = k0; }     else sec1 = fmaxf(sec1, d0[2]);
            if (d0[3] > best1) { sec1 = best1; best1 = d0[3]; bi1 = k0 + 1; } else sec1 = fmaxf(sec1, d0[3]);
            if (d1[2] > best1) { sec1 = best1; best1 = d1[2]; bi1 = k0 + 8; } else sec1 = fmaxf(sec1, d1[2]);
            if (d1[3] > best1) { sec1 = best1; best1 = d1[3]; bi1 = k0 + 9; } else sec1 = fmaxf(sec1, d1[3]);
        }
        __syncthreads();
    }

    // quad merge (lanes c4=0..3 hold disjoint cand residues of the same rows)
#pragma unroll
    for (int off = 1; off <= 2; off <<= 1) {
        float ob = __shfl_xor_sync(0xFFFFFFFFu, best0, off);
        int   oi = __shfl_xor_sync(0xFFFFFFFFu, bi0,   off);
        float os = __shfl_xor_sync(0xFFFFFFFFu, sec0,  off);
        if (ob > best0 || (ob == best0 && oi < bi0)) {
            sec0 = fmaxf(fmaxf(sec0, os), best0); best0 = ob; bi0 = oi;
        } else sec0 = fmaxf(fmaxf(sec0, os), ob);
        ob = __shfl_xor_sync(0xFFFFFFFFu, best1, off);
        oi = __shfl_xor_sync(0xFFFFFFFFu, bi1,   off);
        os = __shfl_xor_sync(0xFFFFFFFFu, sec1,  off);
        if (ob > best1 || (ob == best1 && oi < bi1)) {
            sec1 = fmaxf(fmaxf(sec1, os), best1); best1 = ob; bi1 = oi;
        } else sec1 = fmaxf(fmaxf(sec1, os), ob);
    }

    if (c4 == 0) {
        int r0 = rb + warp * 16 + q;
        if (best0 - sec0 >= DELTA) out[r0] = (float)bi0;
        else { int ix = atomicAdd(&g_dirty_n, 1); g_dirty[ix] = r0; }
        int r1 = r0 + 8;
        if (best1 - sec1 >= DELTA) out[r1] = (float)bi1;
        else { int ix = atomicAdd(&g_dirty_n, 1); g_dirty[ix] = r1; }
    }
}

// ============================================================================
// Kernel 4: exact fp32 rescore of dirty rows (expected ~0.3% of rows).
// One block per dirty entry (strided); first-max via monotone-u64 atomicMax.
// ============================================================================
__global__ __launch_bounds__(256) void cleanup_kernel(const float* __restrict__ CB,
                                                      float* __restrict__ out) {
    __shared__ float vrow[E_DIM];
    __shared__ unsigned long long bestkey;
    const int n = g_dirty_n;
    for (int i = blockIdx.x; i < n; i += gridDim.x) {
        const int row = g_dirty[i];
        if (threadIdx.x == 0) bestkey = 0ull;
        if (threadIdx.x < E_DIM) vrow[threadIdx.x] = g_V[(size_t)row * E_DIM + threadIdx.x];
        __syncthreads();
        float v[E_DIM];
#pragma unroll
        for (int e = 0; e < E_DIM; ++e) v[e] = vrow[e];

        for (int c = threadIdx.x; c < K_CB; c += 256) {
            const float4* cb = (const float4*)(CB + (size_t)c * E_DIM);
            float4 a = cb[0], b = cb[1], cc = cb[2], d = cb[3];
            float t0 = a.x * v[0], t1 = a.y * v[1];
            t0 = fmaf(a.z, v[2],  t0); t1 = fmaf(a.w, v[3],  t1);
            t0 = fmaf(b.x, v[4],  t0); t1 = fmaf(b.y, v[5],  t1);
            t0 = fmaf(b.z, v[6],  t0); t1 = fmaf(b.w, v[7],  t1);
            t0 = fmaf(cc.x, v[8],  t0); t1 = fmaf(cc.y, v[9],  t1);
            t0 = fmaf(cc.z, v[10], t0); t1 = fmaf(cc.w, v[11], t1);
            t0 = fmaf(d.x, v[12], t0); t1 = fmaf(d.y, v[13], t1);
            t0 = fmaf(d.z, v[14], t0); t1 = fmaf(d.w, v[15], t1);
            float s = t0 + t1;
            uint32_t ub = __float_as_uint(s);
            ub = (ub & 0x80000000u) ? ~ub : (ub | 0x80000000u);   // order-preserving
            unsigned long long key = ((unsigned long long)ub << 13) | (unsigned)(8191 - c);
            atomicMax(&bestkey, key);
        }
        __syncthreads();
        if (threadIdx.x == 0)
            out[row] = (float)(8191 - (int)(bestkey & 0x1FFFull));
        __syncthreads();
    }
}

// ============================================================================
extern "C" void kernel_launch(void* const* d_in, const int* in_sizes, int n_in,
                              void* d_out, int out_size) {
    // Input dispatch by element count (ordering-proof):
    //   H = 5,120,000 ; P = 5,120 ; CB = 131,072
    const float* H  = nullptr;
    const float* P  = nullptr;
    const float* CB = nullptr;
    for (int i = 0; i < n_in; ++i) {
        if      (in_sizes[i] == B_T * D_IN)   H  = (const float*)d_in[i];
        else if (in_sizes[i] == D_IN * E_DIM) P  = (const float*)d_in[i];
        else if (in_sizes[i] == K_CB * E_DIM) CB = (const float*)d_in[i];
    }
    if (!H)  H  = (const float*)d_in[0];
    if (!P)  P  = (const float*)d_in[1];
    if (!CB) CB = (const float*)d_in[2];

    float* out = (float*)d_out;   // labels as float VALUES (float32 output buffer)

    proj_split_kernel<<<B_T / 8, 256>>>(H, P);
    cb_split_kernel<<<(K_CB + 255) / 256, 256>>>(CB);
    score_kernel<<<GRID_R, 256>>>(out);
    cleanup_kernel<<<64, 256>>>(CB, out);
}